// round 11
// baseline (speedup 1.0000x reference)
#include <cuda_runtime.h>
#include <cuda_fp16.h>
#include <math.h>
#include <stdint.h>
#include <stddef.h>

#define N_NODES 50000
#define N_EDGES 800000
#define D 64
#define HID 128
#define IN_F 192
#define TM 128
#define BLOCK 512
#define NBLK 152

// padded fp16 row strides (row byte base steps by 16 mod 128 -> conflict-free ldmatrix)
#define XSTR 200     // K=192 + 8 pad
#define HSTR 136     // K=128 + 8 pad
#define W1STR 200
#define W2STR 136

// ---- shared memory byte offsets ----
#define W1H_OFF 0            // [128 n][200 k] fp16 = 51200
#define W1L_OFF 51200
#define W2H_OFF 102400       // [64 n][136 k] fp16 = 17408
#define W2L_OFF 119808
#define X_OFF 137216         // [128 m][200 k] fp16 = 51200
#define H_OFF 188416         // [128 m][136 k] fp16 = 34816
#define B1_OFF 223232        // b1[128] f32
#define B2_OFF 223744        // b2[64] f32
#define G_OFF 224000
#define BETA_OFF 224256
#define RSUM_OFF 224512      // per-row LN partial sum [128]
#define RSQ_OFF 225024       // per-row LN partial sumsq [128]
#define SMEM_BYTES 225536

// scratch for segment-mean aggregation
__device__ __align__(16) float g_acc_u[N_NODES * D];
__device__ __align__(16) float g_acc_v[N_NODES * D];
__device__ float g_cnt_s[N_NODES];
__device__ float g_cnt_d[N_NODES];

// ---------------- helpers ----------------
__device__ __forceinline__ uint32_t smem_u32(const void* p) {
    uint32_t a;
    asm("{ .reg .u64 t; cvta.to.shared.u64 t, %1; cvt.u32.u64 %0, t; }" : "=r"(a) : "l"(p));
    return a;
}
__device__ __forceinline__ void ldsm4(uint32_t* r, uint32_t addr) {
    asm volatile("ldmatrix.sync.aligned.m8n8.x4.shared.b16 {%0,%1,%2,%3}, [%4];"
                 : "=r"(r[0]), "=r"(r[1]), "=r"(r[2]), "=r"(r[3]) : "r"(addr));
}
__device__ __forceinline__ void ldsm2(uint32_t* r, uint32_t addr) {
    asm volatile("ldmatrix.sync.aligned.m8n8.x2.shared.b16 {%0,%1}, [%2];"
                 : "=r"(r[0]), "=r"(r[1]) : "r"(addr));
}
__device__ __forceinline__ void mma16816(float* d, const uint32_t* a, const uint32_t* b) {
    asm volatile("mma.sync.aligned.m16n8k16.row.col.f32.f16.f16.f32 "
                 "{%0,%1,%2,%3}, {%4,%5,%6,%7}, {%8,%9}, {%0,%1,%2,%3};"
                 : "+f"(d[0]), "+f"(d[1]), "+f"(d[2]), "+f"(d[3])
                 : "r"(a[0]), "r"(a[1]), "r"(a[2]), "r"(a[3]), "r"(b[0]), "r"(b[1]));
}
__device__ __forceinline__ uint32_t pack_h2(float a, float b) {
    __half2 h = __floats2half2_rn(a, b);
    return *reinterpret_cast<uint32_t*>(&h);
}
__device__ __forceinline__ float gelu_tanh(float x) {
    float x3 = x * x * x;
    return 0.5f * x * (1.0f + tanhf(0.7978845608028654f * (x + 0.044715f * x3)));
}
__device__ __forceinline__ void red_add_v2(float* addr, float a, float b) {
    asm volatile("red.global.add.v2.f32 [%0], {%1,%2};"
                 :: "l"(addr), "f"(a), "f"(b) : "memory");
}

__global__ void zero_scratch_kernel() {
    int i = blockIdx.x * blockDim.x + threadIdx.x;
    int stride = gridDim.x * blockDim.x;
    const float4 z = make_float4(0.f, 0.f, 0.f, 0.f);
    for (int j = i; j < N_NODES * D / 4; j += stride) {
        ((float4*)g_acc_u)[j] = z;
        ((float4*)g_acc_v)[j] = z;
    }
    for (int j = i; j < N_NODES; j += stride) {
        g_cnt_s[j] = 0.f;
        g_cnt_d[j] = 0.f;
    }
}

template <bool EDGE>
__global__ __launch_bounds__(BLOCK, 1)
void mlp_mma_kernel(const float* __restrict__ ndata,
                    const float* __restrict__ edata,
                    const int* __restrict__ src,
                    const int* __restrict__ dst,
                    const float* __restrict__ W1,   // [192][128]
                    const float* __restrict__ b1,
                    const float* __restrict__ W2,   // [128][64]
                    const float* __restrict__ b2,
                    const float* __restrict__ gam,
                    const float* __restrict__ beta,
                    float* __restrict__ out,
                    int count) {
    extern __shared__ __align__(16) char smc[];
    const uint32_t sb = smem_u32(smc);
    const int tid = threadIdx.x;
    const int w = tid >> 5, l = tid & 31;

    // ---- stage weights transposed to [n][k], fp16 split hi/lo ----
    for (int i = tid; i < IN_F * HID; i += BLOCK) {
        int k = i >> 7, n = i & 127;
        float v = W1[i];
        __half h = __float2half_rn(v);
        __half lo = __float2half_rn(v - __half2float(h));
        uint32_t o = (uint32_t)(n * W1STR + k) * 2;
        *(__half*)(smc + W1H_OFF + o) = h;
        *(__half*)(smc + W1L_OFF + o) = lo;
    }
    for (int i = tid; i < HID * D; i += BLOCK) {
        int k = i >> 6, n = i & 63;
        float v = W2[i];
        __half h = __float2half_rn(v);
        __half lo = __float2half_rn(v - __half2float(h));
        uint32_t o = (uint32_t)(n * W2STR + k) * 2;
        *(__half*)(smc + W2H_OFF + o) = h;
        *(__half*)(smc + W2L_OFF + o) = lo;
    }
    float* b1s = (float*)(smc + B1_OFF);
    float* b2s = (float*)(smc + B2_OFF);
    float* gs = (float*)(smc + G_OFF);
    float* bts = (float*)(smc + BETA_OFF);
    float* rs = (float*)(smc + RSUM_OFF);
    float* rq = (float*)(smc + RSQ_OFF);
    for (int i = tid; i < HID; i += BLOCK) b1s[i] = b1[i];
    for (int i = tid; i < D; i += BLOCK) {
        b2s[i] = b2[i];
        gs[i] = gam[i];
        bts[i] = beta[i];
    }
    __syncthreads();

    const float4* nd4 = (const float4*)ndata;
    const float4* ed4 = (const float4*)edata;

    // lane-invariant ldmatrix address pieces
    const int am = l >> 3;                     // matrix id 0..3
    const int g = l >> 2, t = l & 3;
    const int mw = w >> 3, nw = w & 7;         // 2 m-warps (64 rows each) x 8 n-warps
    const uint32_t aoff1 = (uint32_t)((mw * 64 + (am & 1) * 8 + (l & 7)) * XSTR + (am >> 1) * 8) * 2;
    const uint32_t boff1 = (uint32_t)((nw * 16 + (am >> 1) * 8 + (l & 7)) * W1STR + (am & 1) * 8) * 2;
    const uint32_t aoff2 = (uint32_t)((mw * 64 + (am & 1) * 8 + (l & 7)) * HSTR + (am >> 1) * 8) * 2;
    uint32_t boff2;
    if (l < 8)        boff2 = (uint32_t)((nw * 8 + l) * W2STR) * 2;
    else if (l < 16)  boff2 = (uint32_t)((nw * 8 + (l - 8)) * W2STR + 8) * 2;
    else              boff2 = 0;

    // gather mapping: 4 threads per row, 12 float4 slots each
    const int grow = tid >> 2;                 // 0..127
    const int gslot = tid & 3;

    const int ntiles = (count + TM - 1) / TM;
    for (int tile = blockIdx.x; tile < ntiles; tile += gridDim.x) {
        const int e0 = tile * TM;

        // ---- gather X[128][192] fp32 -> fp16 smem ----
        {
            int idx = e0 + grow;
            bool valid = EDGE || idx < count;
            int sI = 0, dI = 0;
            float invS = 1.f, invD = 1.f;
            if (valid) {
                if (EDGE) {
                    sI = src[idx];
                    dI = dst[idx];
                } else {
                    invS = 1.f / fmaxf(g_cnt_s[idx], 1.f);
                    invD = 1.f / fmaxf(g_cnt_d[idx], 1.f);
                }
            }
            #pragma unroll
            for (int jj = 0; jj < 12; jj++) {
                int seg = gslot + jj * 4;      // 0..47
                float4 v = make_float4(0.f, 0.f, 0.f, 0.f);
                if (valid) {
                    if (EDGE) {
                        if (seg < 16)      v = nd4[(size_t)sI * 16 + seg];
                        else if (seg < 32) v = nd4[(size_t)dI * 16 + (seg - 16)];
                        else               v = ed4[(size_t)idx * 16 + (seg - 32)];
                    } else {
                        if (seg < 16) {
                            float4 a = ((const float4*)g_acc_u)[(size_t)idx * 16 + seg];
                            v = make_float4(a.x * invS, a.y * invS, a.z * invS, a.w * invS);
                        } else if (seg < 32) {
                            float4 a = ((const float4*)g_acc_v)[(size_t)idx * 16 + (seg - 16)];
                            v = make_float4(a.x * invD, a.y * invD, a.z * invD, a.w * invD);
                        } else {
                            v = nd4[(size_t)idx * 16 + (seg - 32)];
                        }
                    }
                }
                uint32_t o = (uint32_t)(grow * XSTR) * 2 + (uint32_t)seg * 8;
                *(uint2*)(smc + X_OFF + o) = make_uint2(pack_h2(v.x, v.y), pack_h2(v.z, v.w));
            }
        }
        __syncthreads();

        // ---- GEMM1: C1[128][128] = X @ (W1hi + W1lo), 2-pass fp16 ----
        float c1[4][2][4];
        #pragma unroll
        for (int mi = 0; mi < 4; mi++)
            #pragma unroll
            for (int ni = 0; ni < 2; ni++)
                #pragma unroll
                for (int q = 0; q < 4; q++) c1[mi][ni][q] = 0.f;
        for (int ks = 0; ks < 12; ks++) {
            const uint32_t ko = (uint32_t)ks * 32;
            uint32_t a[4][4], bh[4], bl[4];
            #pragma unroll
            for (int mi = 0; mi < 4; mi++)
                ldsm4(a[mi], sb + X_OFF + aoff1 + (uint32_t)mi * (16 * XSTR * 2) + ko);
            ldsm4(bh, sb + W1H_OFF + boff1 + ko);
            ldsm4(bl, sb + W1L_OFF + boff1 + ko);
            #pragma unroll
            for (int mi = 0; mi < 4; mi++)
                #pragma unroll
                for (int ni = 0; ni < 2; ni++) {
                    mma16816(c1[mi][ni], a[mi], bh + ni * 2);
                    mma16816(c1[mi][ni], a[mi], bl + ni * 2);
                }
        }

        // ---- epilogue1: +b1, gelu -> H fp16 smem ----
        #pragma unroll
        for (int mi = 0; mi < 4; mi++)
            #pragma unroll
            for (int ni = 0; ni < 2; ni++) {
                int colb = nw * 16 + ni * 8 + t * 2;
                #pragma unroll
                for (int h = 0; h < 2; h++) {
                    int r = mw * 64 + mi * 16 + g + h * 8;
                    float v0 = gelu_tanh(c1[mi][ni][2 * h] + b1s[colb]);
                    float v1 = gelu_tanh(c1[mi][ni][2 * h + 1] + b1s[colb + 1]);
                    *(uint32_t*)(smc + H_OFF + (uint32_t)(r * HSTR + colb) * 2) = pack_h2(v0, v1);
                }
            }
        if (tid < TM) { rs[tid] = 0.f; rq[tid] = 0.f; }
        __syncthreads();

        // ---- GEMM2: C2[128][64] = H @ (W2hi + W2lo), 2-pass ----
        float c2[4][4];
        #pragma unroll
        for (int mi = 0; mi < 4; mi++)
            #pragma unroll
            for (int q = 0; q < 4; q++) c2[mi][q] = 0.f;
        #pragma unroll 2
        for (int ks = 0; ks < 8; ks++) {
            const uint32_t ko = (uint32_t)ks * 32;
            uint32_t a[4][4], bh[2], bl[2];
            #pragma unroll
            for (int mi = 0; mi < 4; mi++)
                ldsm4(a[mi], sb + H_OFF + aoff2 + (uint32_t)mi * (16 * HSTR * 2) + ko);
            ldsm2(bh, sb + W2H_OFF + boff2 + ko);
            ldsm2(bl, sb + W2L_OFF + boff2 + ko);
            #pragma unroll
            for (int mi = 0; mi < 4; mi++) {
                mma16816(c2[mi], a[mi], bh);
                mma16816(c2[mi], a[mi], bl);
            }
        }

        // ---- LN partials (cross-warp via smem atomics) ----
        const int colb2 = nw * 8 + t * 2;
        float vv[4][2][2];
        #pragma unroll
        for (int mi = 0; mi < 4; mi++)
            #pragma unroll
            for (int h = 0; h < 2; h++) {
                float v0 = c2[mi][2 * h] + b2s[colb2];
                float v1 = c2[mi][2 * h + 1] + b2s[colb2 + 1];
                vv[mi][h][0] = v0;
                vv[mi][h][1] = v1;
                float s = v0 + v1, q = v0 * v0 + v1 * v1;
                s += __shfl_xor_sync(0xffffffffu, s, 1);
                q += __shfl_xor_sync(0xffffffffu, q, 1);
                s += __shfl_xor_sync(0xffffffffu, s, 2);
                q += __shfl_xor_sync(0xffffffffu, q, 2);
                if (t == 0) {
                    int r = mw * 64 + mi * 16 + g + h * 8;
                    atomicAdd(&rs[r], s);
                    atomicAdd(&rq[r], q);
                }
            }
        __syncthreads();

        // ---- normalize + writeout (+ scatter for EDGE) ----
        #pragma unroll
        for (int mi = 0; mi < 4; mi++)
            #pragma unroll
            for (int h = 0; h < 2; h++) {
                int r = mw * 64 + mi * 16 + g + h * 8;
                int idx = e0 + r;
                if (EDGE || idx < count) {
                    float mean = rs[r] * (1.f / 64.f);
                    float var = rq[r] * (1.f / 64.f) - mean * mean;
                    float rstd = rsqrtf(var + 1e-5f);
                    float o0 = (vv[mi][h][0] - mean) * rstd * gs[colb2] + bts[colb2];
                    float o1 = (vv[mi][h][1] - mean) * rstd * gs[colb2 + 1] + bts[colb2 + 1];
                    *(float2*)(out + (size_t)idx * D + colb2) = make_float2(o0, o1);
                    if (EDGE) {
                        int sN = src[idx], dN = dst[idx];
                        red_add_v2(g_acc_u + (size_t)sN * D + colb2, o0, o1);
                        red_add_v2(g_acc_v + (size_t)dN * D + colb2, o0, o1);
                        if (nw == 0 && t == 0) {
                            atomicAdd(&g_cnt_s[sN], 1.f);
                            atomicAdd(&g_cnt_d[dN], 1.f);
                        }
                    }
                }
            }
        __syncthreads();
    }
}

extern "C" void kernel_launch(void* const* d_in, const int* in_sizes, int n_in,
                              void* d_out, int out_size) {
    const float* ndata = (const float*)d_in[0];
    const float* edata = (const float*)d_in[1];
    const int* src = (const int*)d_in[2];
    const int* dst = (const int*)d_in[3];
    const float* eW1 = (const float*)d_in[4];
    const float* eb1 = (const float*)d_in[5];
    const float* eW2 = (const float*)d_in[6];
    const float* eb2 = (const float*)d_in[7];
    const float* eg = (const float*)d_in[8];
    const float* ebeta = (const float*)d_in[9];
    const float* nW1 = (const float*)d_in[10];
    const float* nb1 = (const float*)d_in[11];
    const float* nW2 = (const float*)d_in[12];
    const float* nb2 = (const float*)d_in[13];
    const float* ng = (const float*)d_in[14];
    const float* nbeta = (const float*)d_in[15];

    float* out = (float*)d_out;
    float* out_nodes = out;
    float* out_edges = out + (size_t)N_NODES * D;

    void (*kE)(const float*, const float*, const int*, const int*,
               const float*, const float*, const float*, const float*,
               const float*, const float*, float*, int) = mlp_mma_kernel<true>;
    void (*kN)(const float*, const float*, const int*, const int*,
               const float*, const float*, const float*, const float*,
               const float*, const float*, float*, int) = mlp_mma_kernel<false>;
    cudaFuncSetAttribute((const void*)kE, cudaFuncAttributeMaxDynamicSharedMemorySize, SMEM_BYTES);
    cudaFuncSetAttribute((const void*)kN, cudaFuncAttributeMaxDynamicSharedMemorySize, SMEM_BYTES);

    zero_scratch_kernel<<<1024, 256>>>();
    kE<<<NBLK, BLOCK, SMEM_BYTES>>>(ndata, edata, src, dst,
                                    eW1, eb1, eW2, eb2, eg, ebeta,
                                    out_edges, N_EDGES);
    kN<<<NBLK, BLOCK, SMEM_BYTES>>>(ndata, nullptr, nullptr, nullptr,
                                    nW1, nb1, nW2, nb2, ng, nbeta,
                                    out_nodes, N_NODES);
}

// round 12
// speedup vs baseline: 1.4910x; 1.4910x over previous
#include <cuda_runtime.h>
#include <cuda_fp16.h>
#include <math.h>
#include <stdint.h>
#include <stddef.h>

#define N_NODES 50000
#define N_EDGES 800000
#define D 64
#define HID 128
#define IN_F 192
#define TM 64
#define BLOCK 512
#define NBLK 152

// padded fp16 row strides (row byte base steps by 16 mod 128 -> conflict-free ldmatrix)
#define XSTR 200     // K=192 + 8 pad
#define HSTR 136     // K=128 + 8 pad
#define W1STR 200
#define W2STR 136

// ---- shared memory byte offsets ----
#define W1H_OFF 0            // [128 n][200 k] fp16 = 51200
#define W1L_OFF 51200
#define W2H_OFF 102400       // [64 n][136 k] fp16 = 17408
#define W2L_OFF 119808
#define X_OFF 137216         // [64 m][200 k] fp16 = 25600 (single buffer)
#define H_OFF 162816         // [64 m][136 k] fp16 = 17408 (single buffer)
#define B1_OFF 180224        // b1[128] f32
#define B2_OFF 180736        // b2[64] f32
#define G_OFF 180992
#define BETA_OFF 181248
#define RSUM_OFF 181504      // per-row LN partial sum [64]
#define RSQ_OFF 181760       // per-row LN partial sumsq [64]
#define SMEM_BYTES 182016

// scratch for segment-mean aggregation
__device__ __align__(16) float g_acc_u[N_NODES * D];
__device__ __align__(16) float g_acc_v[N_NODES * D];
__device__ float g_cnt_s[N_NODES];
__device__ float g_cnt_d[N_NODES];

// ---------------- helpers ----------------
__device__ __forceinline__ uint32_t smem_u32(const void* p) {
    uint32_t a;
    asm("{ .reg .u64 t; cvta.to.shared.u64 t, %1; cvt.u32.u64 %0, t; }" : "=r"(a) : "l"(p));
    return a;
}
__device__ __forceinline__ void ldsm4(uint32_t* r, uint32_t addr) {
    asm volatile("ldmatrix.sync.aligned.m8n8.x4.shared.b16 {%0,%1,%2,%3}, [%4];"
                 : "=r"(r[0]), "=r"(r[1]), "=r"(r[2]), "=r"(r[3]) : "r"(addr));
}
__device__ __forceinline__ void ldsm2(uint32_t* r, uint32_t addr) {
    asm volatile("ldmatrix.sync.aligned.m8n8.x2.shared.b16 {%0,%1}, [%2];"
                 : "=r"(r[0]), "=r"(r[1]) : "r"(addr));
}
__device__ __forceinline__ void mma16816(float* d, const uint32_t* a, const uint32_t* b) {
    asm volatile("mma.sync.aligned.m16n8k16.row.col.f32.f16.f16.f32 "
                 "{%0,%1,%2,%3}, {%4,%5,%6,%7}, {%8,%9}, {%0,%1,%2,%3};"
                 : "+f"(d[0]), "+f"(d[1]), "+f"(d[2]), "+f"(d[3])
                 : "r"(a[0]), "r"(a[1]), "r"(a[2]), "r"(a[3]), "r"(b[0]), "r"(b[1]));
}
__device__ __forceinline__ uint32_t pack_h2(float a, float b) {
    __half2 h = __floats2half2_rn(a, b);
    return *reinterpret_cast<uint32_t*>(&h);
}
// tanh-GELU via identity 0.5*x*(1+tanh(z)) == x * sigmoid(2*z)
__device__ __forceinline__ float gelu_fast(float x) {
    float z2 = 1.5957691216057308f * x * (1.0f + 0.044715f * x * x);  // 2*sqrt(2/pi)*(x+c x^3)/x form
    return __fdividef(x, 1.0f + __expf(-z2));
}
__device__ __forceinline__ void red_add_v2(float* addr, float a, float b) {
    asm volatile("red.global.add.v2.f32 [%0], {%1,%2};"
                 :: "l"(addr), "f"(a), "f"(b) : "memory");
}

__global__ void zero_scratch_kernel() {
    int i = blockIdx.x * blockDim.x + threadIdx.x;
    int stride = gridDim.x * blockDim.x;
    const float4 z = make_float4(0.f, 0.f, 0.f, 0.f);
    for (int j = i; j < N_NODES * D / 4; j += stride) {
        ((float4*)g_acc_u)[j] = z;
        ((float4*)g_acc_v)[j] = z;
    }
    for (int j = i; j < N_NODES; j += stride) {
        g_cnt_s[j] = 0.f;
        g_cnt_d[j] = 0.f;
    }
}

template <bool EDGE>
__global__ __launch_bounds__(BLOCK, 1)
void mlp_mma_kernel(const float* __restrict__ ndata,
                    const float* __restrict__ edata,
                    const int* __restrict__ src,
                    const int* __restrict__ dst,
                    const float* __restrict__ W1,   // [192][128]
                    const float* __restrict__ b1,
                    const float* __restrict__ W2,   // [128][64]
                    const float* __restrict__ b2,
                    const float* __restrict__ gam,
                    const float* __restrict__ beta,
                    float* __restrict__ out,
                    int count) {
    extern __shared__ __align__(16) char smc[];
    const uint32_t sb = smem_u32(smc);
    const int tid = threadIdx.x;
    const int w = tid >> 5, l = tid & 31;

    // ---- stage weights transposed to [n][k], fp16 split hi/lo ----
    for (int i = tid; i < IN_F * HID; i += BLOCK) {
        int k = i >> 7, n = i & 127;
        float v = W1[i];
        __half h = __float2half_rn(v);
        __half lo = __float2half_rn(v - __half2float(h));
        uint32_t o = (uint32_t)(n * W1STR + k) * 2;
        *(__half*)(smc + W1H_OFF + o) = h;
        *(__half*)(smc + W1L_OFF + o) = lo;
    }
    for (int i = tid; i < HID * D; i += BLOCK) {
        int k = i >> 6, n = i & 63;
        float v = W2[i];
        __half h = __float2half_rn(v);
        __half lo = __float2half_rn(v - __half2float(h));
        uint32_t o = (uint32_t)(n * W2STR + k) * 2;
        *(__half*)(smc + W2H_OFF + o) = h;
        *(__half*)(smc + W2L_OFF + o) = lo;
    }
    float* b1s = (float*)(smc + B1_OFF);
    float* b2s = (float*)(smc + B2_OFF);
    float* gs = (float*)(smc + G_OFF);
    float* bts = (float*)(smc + BETA_OFF);
    float* rs = (float*)(smc + RSUM_OFF);
    float* rq = (float*)(smc + RSQ_OFF);
    for (int i = tid; i < HID; i += BLOCK) b1s[i] = b1[i];
    for (int i = tid; i < D; i += BLOCK) {
        b2s[i] = b2[i];
        gs[i] = gam[i];
        bts[i] = beta[i];
    }
    __syncthreads();

    const float4* nd4 = (const float4*)ndata;
    const float4* ed4 = (const float4*)edata;

    // lane-invariant ldmatrix address pieces
    const int am = l >> 3;                     // matrix id 0..3
    const int g = l >> 2, t = l & 3;
    const int mw = w >> 3, nw = w & 7;         // 2 m-warps x 8 n-warps
    const uint32_t aoff1 = (uint32_t)((mw * 32 + (am & 1) * 8 + (l & 7)) * XSTR + (am >> 1) * 8) * 2;
    const uint32_t boff1 = (uint32_t)((nw * 16 + (am >> 1) * 8 + (l & 7)) * W1STR + (am & 1) * 8) * 2;
    const uint32_t aoff2 = (uint32_t)((mw * 32 + (am & 1) * 8 + (l & 7)) * HSTR + (am >> 1) * 8) * 2;
    uint32_t boff2;
    if (l < 8)        boff2 = (uint32_t)((nw * 8 + l) * W2STR) * 2;
    else if (l < 16)  boff2 = (uint32_t)((nw * 8 + (l - 8)) * W2STR + 8) * 2;
    else              boff2 = 0;

    // gather mapping: 8 threads per row, 6 float4 slots each
    const int grow = tid >> 3;                 // 0..63
    const int gslot = tid & 7;

    const int ntiles = (count + TM - 1) / TM;
    for (int tile = blockIdx.x; tile < ntiles; tile += gridDim.x) {
        const int e0 = tile * TM;

        // ---- gather X[64][192] fp32 -> fp16 smem (single buffer) ----
        {
            int idx = e0 + grow;
            bool valid = EDGE || idx < count;
            int sI = 0, dI = 0;
            float invS = 1.f, invD = 1.f;
            if (valid) {
                if (EDGE) {
                    sI = src[idx];
                    dI = dst[idx];
                } else {
                    invS = 1.f / fmaxf(g_cnt_s[idx], 1.f);
                    invD = 1.f / fmaxf(g_cnt_d[idx], 1.f);
                }
            }
            #pragma unroll
            for (int jj = 0; jj < 6; jj++) {
                int seg = gslot + jj * 8;      // 0..47
                float4 v = make_float4(0.f, 0.f, 0.f, 0.f);
                if (valid) {
                    if (EDGE) {
                        if (seg < 16)      v = nd4[(size_t)sI * 16 + seg];
                        else if (seg < 32) v = nd4[(size_t)dI * 16 + (seg - 16)];
                        else               v = ed4[(size_t)idx * 16 + (seg - 32)];
                    } else {
                        if (seg < 16) {
                            float4 a = ((const float4*)g_acc_u)[(size_t)idx * 16 + seg];
                            v = make_float4(a.x * invS, a.y * invS, a.z * invS, a.w * invS);
                        } else if (seg < 32) {
                            float4 a = ((const float4*)g_acc_v)[(size_t)idx * 16 + (seg - 16)];
                            v = make_float4(a.x * invD, a.y * invD, a.z * invD, a.w * invD);
                        } else {
                            v = nd4[(size_t)idx * 16 + (seg - 32)];
                        }
                    }
                }
                uint32_t o = (uint32_t)(grow * XSTR) * 2 + (uint32_t)seg * 8;
                *(uint2*)(smc + X_OFF + o) = make_uint2(pack_h2(v.x, v.y), pack_h2(v.z, v.w));
            }
        }
        __syncthreads();

        // ---- GEMM1: C1[64][128] = X @ (W1hi + W1lo), 2-pass fp16 ----
        float c1[2][2][4];
        #pragma unroll
        for (int mi = 0; mi < 2; mi++)
            #pragma unroll
            for (int ni = 0; ni < 2; ni++)
                #pragma unroll
                for (int q = 0; q < 4; q++) c1[mi][ni][q] = 0.f;
        #pragma unroll 2
        for (int ks = 0; ks < 12; ks++) {
            const uint32_t ko = (uint32_t)ks * 32;
            uint32_t a[2][4], bh[4], bl[4];
            ldsm4(a[0], sb + X_OFF + aoff1 + ko);
            ldsm4(a[1], sb + X_OFF + aoff1 + 16 * XSTR * 2 + ko);
            ldsm4(bh, sb + W1H_OFF + boff1 + ko);
            ldsm4(bl, sb + W1L_OFF + boff1 + ko);
            #pragma unroll
            for (int mi = 0; mi < 2; mi++)
                #pragma unroll
                for (int ni = 0; ni < 2; ni++) {
                    mma16816(c1[mi][ni], a[mi], bh + ni * 2);
                    mma16816(c1[mi][ni], a[mi], bl + ni * 2);
                }
        }

        // ---- epilogue1: +b1, fast gelu -> H fp16 smem ----
        #pragma unroll
        for (int mi = 0; mi < 2; mi++)
            #pragma unroll
            for (int ni = 0; ni < 2; ni++) {
                int colb = nw * 16 + ni * 8 + t * 2;
                #pragma unroll
                for (int h = 0; h < 2; h++) {
                    int r = mw * 32 + mi * 16 + g + h * 8;
                    float v0 = gelu_fast(c1[mi][ni][2 * h] + b1s[colb]);
                    float v1 = gelu_fast(c1[mi][ni][2 * h + 1] + b1s[colb + 1]);
                    *(uint32_t*)(smc + H_OFF + (uint32_t)(r * HSTR + colb) * 2) = pack_h2(v0, v1);
                }
            }
        if (tid < TM) { rs[tid] = 0.f; rq[tid] = 0.f; }
        __syncthreads();

        // ---- GEMM2: C2[64][64] = H @ (W2hi + W2lo), 2-pass ----
        float c2[2][4];
        #pragma unroll
        for (int mi = 0; mi < 2; mi++)
            #pragma unroll
            for (int q = 0; q < 4; q++) c2[mi][q] = 0.f;
        #pragma unroll 2
        for (int ks = 0; ks < 8; ks++) {
            const uint32_t ko = (uint32_t)ks * 32;
            uint32_t a[2][4], bh[2], bl[2];
            ldsm4(a[0], sb + H_OFF + aoff2 + ko);
            ldsm4(a[1], sb + H_OFF + aoff2 + 16 * HSTR * 2 + ko);
            ldsm2(bh, sb + W2H_OFF + boff2 + ko);
            ldsm2(bl, sb + W2L_OFF + boff2 + ko);
            #pragma unroll
            for (int mi = 0; mi < 2; mi++) {
                mma16816(c2[mi], a[mi], bh);
                mma16816(c2[mi], a[mi], bl);
            }
        }

        // ---- LN partials (cross-warp via smem atomics) ----
        const int colb2 = nw * 8 + t * 2;
        float vv[2][2][2];
        #pragma unroll
        for (int mi = 0; mi < 2; mi++)
            #pragma unroll
            for (int h = 0; h < 2; h++) {
                float v0 = c2[mi][2 * h] + b2s[colb2];
                float v1 = c2[mi][2 * h + 1] + b2s[colb2 + 1];
                vv[mi][h][0] = v0;
                vv[mi][h][1] = v1;
                float s = v0 + v1, q = v0 * v0 + v1 * v1;
                s += __shfl_xor_sync(0xffffffffu, s, 1);
                q += __shfl_xor_sync(0xffffffffu, q, 1);
                s += __shfl_xor_sync(0xffffffffu, s, 2);
                q += __shfl_xor_sync(0xffffffffu, q, 2);
                if (t == 0) {
                    int r = mw * 32 + mi * 16 + g + h * 8;
                    atomicAdd(&rs[r], s);
                    atomicAdd(&rq[r], q);
                }
            }
        __syncthreads();

        // ---- normalize + writeout (+ scatter for EDGE) ----
        #pragma unroll
        for (int mi = 0; mi < 2; mi++)
            #pragma unroll
            for (int h = 0; h < 2; h++) {
                int r = mw * 32 + mi * 16 + g + h * 8;
                int idx = e0 + r;
                if (EDGE || idx < count) {
                    float mean = rs[r] * (1.f / 64.f);
                    float var = rq[r] * (1.f / 64.f) - mean * mean;
                    float rstd = rsqrtf(var + 1e-5f);
                    float o0 = (vv[mi][h][0] - mean) * rstd * gs[colb2] + bts[colb2];
                    float o1 = (vv[mi][h][1] - mean) * rstd * gs[colb2 + 1] + bts[colb2 + 1];
                    *(float2*)(out + (size_t)idx * D + colb2) = make_float2(o0, o1);
                    if (EDGE) {
                        int sN = src[idx], dN = dst[idx];
                        red_add_v2(g_acc_u + (size_t)sN * D + colb2, o0, o1);
                        red_add_v2(g_acc_v + (size_t)dN * D + colb2, o0, o1);
                        if (nw == 0 && t == 0) {
                            atomicAdd(&g_cnt_s[sN], 1.f);
                            atomicAdd(&g_cnt_d[dN], 1.f);
                        }
                    }
                }
            }
        __syncthreads();
    }
}

extern "C" void kernel_launch(void* const* d_in, const int* in_sizes, int n_in,
                              void* d_out, int out_size) {
    const float* ndata = (const float*)d_in[0];
    const float* edata = (const float*)d_in[1];
    const int* src = (const int*)d_in[2];
    const int* dst = (const int*)d_in[3];
    const float* eW1 = (const float*)d_in[4];
    const float* eb1 = (const float*)d_in[5];
    const float* eW2 = (const float*)d_in[6];
    const float* eb2 = (const float*)d_in[7];
    const float* eg = (const float*)d_in[8];
    const float* ebeta = (const float*)d_in[9];
    const float* nW1 = (const float*)d_in[10];
    const float* nb1 = (const float*)d_in[11];
    const float* nW2 = (const float*)d_in[12];
    const float* nb2 = (const float*)d_in[13];
    const float* ng = (const float*)d_in[14];
    const float* nbeta = (const float*)d_in[15];

    float* out = (float*)d_out;
    float* out_nodes = out;
    float* out_edges = out + (size_t)N_NODES * D;

    void (*kE)(const float*, const float*, const int*, const int*,
               const float*, const float*, const float*, const float*,
               const float*, const float*, float*, int) = mlp_mma_kernel<true>;
    void (*kN)(const float*, const float*, const int*, const int*,
               const float*, const float*, const float*, const float*,
               const float*, const float*, float*, int) = mlp_mma_kernel<false>;
    cudaFuncSetAttribute((const void*)kE, cudaFuncAttributeMaxDynamicSharedMemorySize, SMEM_BYTES);
    cudaFuncSetAttribute((const void*)kN, cudaFuncAttributeMaxDynamicSharedMemorySize, SMEM_BYTES);

    zero_scratch_kernel<<<1024, 256>>>();
    kE<<<NBLK, BLOCK, SMEM_BYTES>>>(ndata, edata, src, dst,
                                    eW1, eb1, eW2, eb2, eg, ebeta,
                                    out_edges, N_EDGES);
    kN<<<NBLK, BLOCK, SMEM_BYTES>>>(ndata, nullptr, nullptr, nullptr,
                                    nW1, nb1, nW2, nb2, ng, nbeta,
                                    out_nodes, N_NODES);
}

// round 14
// speedup vs baseline: 1.5905x; 1.0667x over previous
#include <cuda_runtime.h>
#include <cuda_fp16.h>
#include <math.h>
#include <stdint.h>
#include <stddef.h>

#define N_NODES 50000
#define N_EDGES 800000
#define D 64
#define HID 128
#define IN_F 192
#define TM 64
#define BLOCK 512
#define NBLK 152

// padded fp16 row strides (row byte base steps by 16 mod 128 -> conflict-free ldmatrix)
#define XSTR 200     // K=192 + 8 pad
#define HSTR 136     // K=128 + 8 pad
#define W1STR 200
#define W2STR 136

// ---- shared memory byte offsets ----
#define W1H_OFF 0            // [128 n][200 k] fp16 = 51200
#define W1L_OFF 51200
#define W2H_OFF 102400       // [64 n][136 k] fp16 = 17408
#define W2L_OFF 119808
#define X_OFF 137216         // [64 m][200 k] fp16 = 25600 (single buffer)
#define H_OFF 162816         // [64 m][136 k] fp16 = 17408 (single buffer)
#define B1_OFF 180224        // b1[128] f32
#define B2_OFF 180736        // b2[64] f32
#define G_OFF 180992
#define BETA_OFF 181248
#define RSUM_OFF 181504      // per-row LN partial sum [64]
#define RSQ_OFF 181760       // per-row LN partial sumsq [64]
#define SMEM_BYTES 182016

// scratch for segment-mean aggregation
__device__ __align__(16) float g_acc_u[N_NODES * D];
__device__ __align__(16) float g_acc_v[N_NODES * D];
__device__ float g_cnt_s[N_NODES];
__device__ float g_cnt_d[N_NODES];

// ---------------- helpers ----------------
__device__ __forceinline__ uint32_t smem_u32(const void* p) {
    uint32_t a;
    asm("{ .reg .u64 t; cvta.to.shared.u64 t, %1; cvt.u32.u64 %0, t; }" : "=r"(a) : "l"(p));
    return a;
}
__device__ __forceinline__ void ldsm4(uint32_t* r, uint32_t addr) {
    asm volatile("ldmatrix.sync.aligned.m8n8.x4.shared.b16 {%0,%1,%2,%3}, [%4];"
                 : "=r"(r[0]), "=r"(r[1]), "=r"(r[2]), "=r"(r[3]) : "r"(addr));
}
__device__ __forceinline__ void ldsm2(uint32_t* r, uint32_t addr) {
    asm volatile("ldmatrix.sync.aligned.m8n8.x2.shared.b16 {%0,%1}, [%2];"
                 : "=r"(r[0]), "=r"(r[1]) : "r"(addr));
}
__device__ __forceinline__ void mma16816(float* d, const uint32_t* a, const uint32_t* b) {
    asm volatile("mma.sync.aligned.m16n8k16.row.col.f32.f16.f16.f32 "
                 "{%0,%1,%2,%3}, {%4,%5,%6,%7}, {%8,%9}, {%0,%1,%2,%3};"
                 : "+f"(d[0]), "+f"(d[1]), "+f"(d[2]), "+f"(d[3])
                 : "r"(a[0]), "r"(a[1]), "r"(a[2]), "r"(a[3]), "r"(b[0]), "r"(b[1]));
}
__device__ __forceinline__ uint32_t pack_h2(float a, float b) {
    __half2 h = __floats2half2_rn(a, b);
    return *reinterpret_cast<uint32_t*>(&h);
}
// tanh-GELU via identity 0.5*x*(1+tanh(z)) == x * sigmoid(2*z)
__device__ __forceinline__ float gelu_fast(float x) {
    float z2 = 1.5957691216057308f * x * (1.0f + 0.044715f * x * x);
    return __fdividef(x, 1.0f + __expf(-z2));
}
__device__ __forceinline__ void red_add_v2(float* addr, float a, float b) {
    asm volatile("red.global.add.v2.f32 [%0], {%1,%2};"
                 :: "l"(addr), "f"(a), "f"(b) : "memory");
}

__global__ void zero_scratch_kernel() {
    int i = blockIdx.x * blockDim.x + threadIdx.x;
    int stride = gridDim.x * blockDim.x;
    const float4 z = make_float4(0.f, 0.f, 0.f, 0.f);
    for (int j = i; j < N_NODES * D / 4; j += stride) {
        ((float4*)g_acc_u)[j] = z;
        ((float4*)g_acc_v)[j] = z;
    }
    for (int j = i; j < N_NODES; j += stride) {
        g_cnt_s[j] = 0.f;
        g_cnt_d[j] = 0.f;
    }
}

template <bool EDGE>
__global__ __launch_bounds__(BLOCK, 1)
void mlp_mma_kernel(const float* __restrict__ ndata,
                    const float* __restrict__ edata,
                    const int* __restrict__ src,
                    const int* __restrict__ dst,
                    const float* __restrict__ W1,   // [192][128]
                    const float* __restrict__ b1,
                    const float* __restrict__ W2,   // [128][64]
                    const float* __restrict__ b2,
                    const float* __restrict__ gam,
                    const float* __restrict__ beta,
                    float* __restrict__ out,
                    int count) {
    extern __shared__ __align__(16) char smc[];
    const uint32_t sb = smem_u32(smc);
    const int tid = threadIdx.x;
    const int w = tid >> 5, l = tid & 31;

    // ---- stage weights transposed to [n][k], fp16 split hi/lo ----
    for (int i = tid; i < IN_F * HID; i += BLOCK) {
        int k = i >> 7, n = i & 127;
        float v = W1[i];
        __half h = __float2half_rn(v);
        __half lo = __float2half_rn(v - __half2float(h));
        uint32_t o = (uint32_t)(n * W1STR + k) * 2;
        *(__half*)(smc + W1H_OFF + o) = h;
        *(__half*)(smc + W1L_OFF + o) = lo;
    }
    for (int i = tid; i < HID * D; i += BLOCK) {
        int k = i >> 6, n = i & 63;
        float v = W2[i];
        __half h = __float2half_rn(v);
        __half lo = __float2half_rn(v - __half2float(h));
        uint32_t o = (uint32_t)(n * W2STR + k) * 2;
        *(__half*)(smc + W2H_OFF + o) = h;
        *(__half*)(smc + W2L_OFF + o) = lo;
    }
    float* b1s = (float*)(smc + B1_OFF);
    float* b2s = (float*)(smc + B2_OFF);
    float* gs = (float*)(smc + G_OFF);
    float* bts = (float*)(smc + BETA_OFF);
    float* rs = (float*)(smc + RSUM_OFF);
    float* rq = (float*)(smc + RSQ_OFF);
    for (int i = tid; i < HID; i += BLOCK) b1s[i] = b1[i];
    for (int i = tid; i < D; i += BLOCK) {
        b2s[i] = b2[i];
        gs[i] = gam[i];
        bts[i] = beta[i];
    }

    const float4* nd4 = (const float4*)ndata;
    const float4* ed4 = (const float4*)edata;

    // lane-invariant ldmatrix address pieces
    const int am = l >> 3;                     // matrix id 0..3
    const int g = l >> 2, t = l & 3;
    const int mw = w >> 3, nw = w & 7;         // 2 m-warps x 8 n-warps
    const uint32_t aoff1 = (uint32_t)((mw * 32 + (am & 1) * 8 + (l & 7)) * XSTR + (am >> 1) * 8) * 2;
    const uint32_t boff1 = (uint32_t)((nw * 16 + (am >> 1) * 8 + (l & 7)) * W1STR + (am & 1) * 8) * 2;
    const uint32_t aoff2 = (uint32_t)((mw * 32 + (am & 1) * 8 + (l & 7)) * HSTR + (am >> 1) * 8) * 2;
    uint32_t boff2;
    if (l < 8)        boff2 = (uint32_t)((nw * 8 + l) * W2STR) * 2;
    else if (l < 16)  boff2 = (uint32_t)((nw * 8 + (l - 8)) * W2STR + 8) * 2;
    else              boff2 = 0;

    // gather mapping: 8 threads per row, 6 float4 slots each
    const int grow = tid >> 3;                 // 0..63
    const int gslot = tid & 7;

    const int ntiles = (count + TM - 1) / TM;

    float4 vbuf[6];

    // load one tile's X slice into registers (LDG only, no smem)
    auto load_regs = [&](int tile_) {
        int idx = tile_ * TM + grow;
        bool valid = EDGE || idx < count;
        int sI = 0, dI = 0;
        float invS = 1.f, invD = 1.f;
        if (valid) {
            if (EDGE) {
                sI = src[idx];
                dI = dst[idx];
            } else {
                invS = 1.f / fmaxf(g_cnt_s[idx], 1.f);
                invD = 1.f / fmaxf(g_cnt_d[idx], 1.f);
            }
        }
        #pragma unroll
        for (int jj = 0; jj < 6; jj++) {
            int seg = gslot + jj * 8;          // 0..47
            float4 v = make_float4(0.f, 0.f, 0.f, 0.f);
            if (valid) {
                if (EDGE) {
                    if (seg < 16)      v = nd4[(size_t)sI * 16 + seg];
                    else if (seg < 32) v = nd4[(size_t)dI * 16 + (seg - 16)];
                    else               v = ed4[(size_t)idx * 16 + (seg - 32)];
                } else {
                    if (seg < 16) {
                        float4 a = ((const float4*)g_acc_u)[(size_t)idx * 16 + seg];
                        v = make_float4(a.x * invS, a.y * invS, a.z * invS, a.w * invS);
                    } else if (seg < 32) {
                        float4 a = ((const float4*)g_acc_v)[(size_t)idx * 16 + (seg - 16)];
                        v = make_float4(a.x * invD, a.y * invD, a.z * invD, a.w * invD);
                    } else {
                        v = nd4[(size_t)idx * 16 + (seg - 32)];
                    }
                }
            }
            vbuf[jj] = v;
        }
    };
    // convert registers -> fp16 X smem
    auto store_smem = [&]() {
        #pragma unroll
        for (int jj = 0; jj < 6; jj++) {
            int seg = gslot + jj * 8;
            uint32_t o = (uint32_t)(grow * XSTR) * 2 + (uint32_t)seg * 8;
            *(uint2*)(smc + X_OFF + o) =
                make_uint2(pack_h2(vbuf[jj].x, vbuf[jj].y), pack_h2(vbuf[jj].z, vbuf[jj].w));
        }
    };

    int tile = blockIdx.x;
    if (tile < ntiles) {
        load_regs(tile);
        store_smem();
    }
    __syncthreads();

    while (tile < ntiles) {
        const int e0 = tile * TM;
        const int nxt = tile + gridDim.x;
        const bool have_next = nxt < ntiles;

        // issue next tile's LDGs early; latency hides under GEMM1
        if (have_next) load_regs(nxt);

        // ---- GEMM1: C1[64][128] = X @ (W1hi + W1lo), 2-pass fp16 ----
        float c1[2][2][4];
        #pragma unroll
        for (int mi = 0; mi < 2; mi++)
            #pragma unroll
            for (int ni = 0; ni < 2; ni++)
                #pragma unroll
                for (int q = 0; q < 4; q++) c1[mi][ni][q] = 0.f;
        #pragma unroll 2
        for (int ks = 0; ks < 12; ks++) {
            const uint32_t ko = (uint32_t)ks * 32;
            uint32_t a[2][4], bh[4], bl[4];
            ldsm4(a[0], sb + X_OFF + aoff1 + ko);
            ldsm4(a[1], sb + X_OFF + aoff1 + 16 * XSTR * 2 + ko);
            ldsm4(bh, sb + W1H_OFF + boff1 + ko);
            ldsm4(bl, sb + W1L_OFF + boff1 + ko);
            #pragma unroll
            for (int mi = 0; mi < 2; mi++)
                #pragma unroll
                for (int ni = 0; ni < 2; ni++) {
                    mma16816(c1[mi][ni], a[mi], bh + ni * 2);
                    mma16816(c1[mi][ni], a[mi], bl + ni * 2);
                }
        }

        // ---- epilogue1: +b1, fast gelu -> H fp16 smem ----
        #pragma unroll
        for (int mi = 0; mi < 2; mi++)
            #pragma unroll
            for (int ni = 0; ni < 2; ni++) {
                int colb = nw * 16 + ni * 8 + t * 2;
                #pragma unroll
                for (int h = 0; h < 2; h++) {
                    int r = mw * 32 + mi * 16 + g + h * 8;
                    float v0 = gelu_fast(c1[mi][ni][2 * h] + b1s[colb]);
                    float v1 = gelu_fast(c1[mi][ni][2 * h + 1] + b1s[colb + 1]);
                    *(uint32_t*)(smc + H_OFF + (uint32_t)(r * HSTR + colb) * 2) = pack_h2(v0, v1);
                }
            }
        if (tid < TM) { rs[tid] = 0.f; rq[tid] = 0.f; }
        __syncthreads();

        // X(tile) is dead now (GEMM1 complete in all warps): stage X(nxt)
        if (have_next) store_smem();

        // ---- GEMM2: C2[64][64] = H @ (W2hi + W2lo), 2-pass ----
        float c2[2][4];
        #pragma unroll
        for (int mi = 0; mi < 2; mi++)
            #pragma unroll
            for (int q = 0; q < 4; q++) c2[mi][q] = 0.f;
        #pragma unroll 2
        for (int ks = 0; ks < 8; ks++) {
            const uint32_t ko = (uint32_t)ks * 32;
            uint32_t a[2][4], bh[2], bl[2];
            ldsm4(a[0], sb + H_OFF + aoff2 + ko);
            ldsm4(a[1], sb + H_OFF + aoff2 + 16 * HSTR * 2 + ko);
            ldsm2(bh, sb + W2H_OFF + boff2 + ko);
            ldsm2(bl, sb + W2L_OFF + boff2 + ko);
            #pragma unroll
            for (int mi = 0; mi < 2; mi++) {
                mma16816(c2[mi], a[mi], bh);
                mma16816(c2[mi], a[mi], bl);
            }
        }

        // ---- LN partials (cross-warp via smem atomics) ----
        const int colb2 = nw * 8 + t * 2;
        float vv[2][2][2];
        #pragma unroll
        for (int mi = 0; mi < 2; mi++)
            #pragma unroll
            for (int h = 0; h < 2; h++) {
                float v0 = c2[mi][2 * h] + b2s[colb2];
                float v1 = c2[mi][2 * h + 1] + b2s[colb2 + 1];
                vv[mi][h][0] = v0;
                vv[mi][h][1] = v1;
                float s = v0 + v1, q = v0 * v0 + v1 * v1;
                s += __shfl_xor_sync(0xffffffffu, s, 1);
                q += __shfl_xor_sync(0xffffffffu, q, 1);
                s += __shfl_xor_sync(0xffffffffu, s, 2);
                q += __shfl_xor_sync(0xffffffffu, q, 2);
                if (t == 0) {
                    int r = mw * 32 + mi * 16 + g + h * 8;
                    atomicAdd(&rs[r], s);
                    atomicAdd(&rq[r], q);
                }
            }
        __syncthreads();

        // ---- normalize + writeout (+ scatter for EDGE) ----
        #pragma unroll
        for (int mi = 0; mi < 2; mi++)
            #pragma unroll
            for (int h = 0; h < 2; h++) {
                int r = mw * 32 + mi * 16 + g + h * 8;
                int idx = e0 + r;
                if (EDGE || idx < count) {
                    float mean = rs[r] * (1.f / 64.f);
                    float var = rq[r] * (1.f / 64.f) - mean * mean;
                    float rstd = rsqrtf(var + 1e-5f);
                    float o0 = (vv[mi][h][0] - mean) * rstd * gs[colb2] + bts[colb2];
                    float o1 = (vv[mi][h][1] - mean) * rstd * gs[colb2 + 1] + bts[colb2 + 1];
                    *(float2*)(out + (size_t)idx * D + colb2) = make_float2(o0, o1);
                    if (EDGE) {
                        int sN = src[idx], dN = dst[idx];
                        red_add_v2(g_acc_u + (size_t)sN * D + colb2, o0, o1);
                        red_add_v2(g_acc_v + (size_t)dN * D + colb2, o0, o1);
                        if (nw == 0 && t == 0) {
                            atomicAdd(&g_cnt_s[sN], 1.f);
                            atomicAdd(&g_cnt_d[dN], 1.f);
                        }
                    }
                }
            }
        __syncthreads();
        tile = nxt;
    }
}

extern "C" void kernel_launch(void* const* d_in, const int* in_sizes, int n_in,
                              void* d_out, int out_size) {
    const float* ndata = (const float*)d_in[0];
    const float* edata = (const float*)d_in[1];
    const int* src = (const int*)d_in[2];
    const int* dst = (const int*)d_in[3];
    const float* eW1 = (const float*)d_in[4];
    const float* eb1 = (const float*)d_in[5];
    const float* eW2 = (const float*)d_in[6];
    const float* eb2 = (const float*)d_in[7];
    const float* eg = (const float*)d_in[8];
    const float* ebeta = (const float*)d_in[9];
    const float* nW1 = (const float*)d_in[10];
    const float* nb1 = (const float*)d_in[11];
    const float* nW2 = (const float*)d_in[12];
    const float* nb2 = (const float*)d_in[13];
    const float* ng = (const float*)d_in[14];
    const float* nbeta = (const float*)d_in[15];

    float* out = (float*)d_out;
    float* out_nodes = out;
    float* out_edges = out + (size_t)N_NODES * D;

    void (*kE)(const float*, const float*, const int*, const int*,
               const float*, const float*, const float*, const float*,
               const float*, const float*, float*, int) = mlp_mma_kernel<true>;
    void (*kN)(const float*, const float*, const int*, const int*,
               const float*, const float*, const float*, const float*,
               const float*, const float*, float*, int) = mlp_mma_kernel<false>;
    cudaFuncSetAttribute((const void*)kE, cudaFuncAttributeMaxDynamicSharedMemorySize, SMEM_BYTES);
    cudaFuncSetAttribute((const void*)kN, cudaFuncAttributeMaxDynamicSharedMemorySize, SMEM_BYTES);

    zero_scratch_kernel<<<1024, 256>>>();
    kE<<<NBLK, BLOCK, SMEM_BYTES>>>(ndata, edata, src, dst,
                                    eW1, eb1, eW2, eb2, eg, ebeta,
                                    out_edges, N_EDGES);
    kN<<<NBLK, BLOCK, SMEM_BYTES>>>(ndata, nullptr, nullptr, nullptr,
                                    nW1, nb1, nW2, nb2, ng, nbeta,
                                    out_nodes, N_NODES);
}

// round 16
// speedup vs baseline: 1.8760x; 1.1795x over previous
#include <cuda_runtime.h>
#include <cuda_fp16.h>
#include <math.h>
#include <stdint.h>
#include <stddef.h>

#define N_NODES 50000
#define N_EDGES 800000
#define D 64
#define HID 128
#define IN_F 192
#define TM 64
#define BLOCK 512
#define NBLK 152

// padded fp16 row strides (row byte base steps by 16 mod 128 -> conflict-free ldmatrix)
#define XSTR 200     // K=192 + 8 pad
#define HSTR 136     // K=128 + 8 pad
#define W1STR 200
#define W2STR 136
#define W2NB (8 * W2STR * 2)   // byte stride between n8 blocks of W2

// ---- shared memory byte offsets ----
#define W1H_OFF 0            // [128 n][200 k] fp16 = 51200
#define W1L_OFF 51200
#define W2H_OFF 102400       // [64 n][136 k] fp16 = 17408
#define W2L_OFF 119808
#define X_OFF 137216         // [64 m][200 k] fp16 = 25600 (single buffer)
#define H_OFF 162816         // [64 m][136 k] fp16 = 17408 (single buffer)
#define B1_OFF 180224        // b1[128] f32
#define B2_OFF 180736        // b2[64] f32
#define G_OFF 180992
#define BETA_OFF 181248
#define SMEM_BYTES 181504

// scratch for segment-mean aggregation
__device__ __align__(16) float g_acc_u[N_NODES * D];
__device__ __align__(16) float g_acc_v[N_NODES * D];
__device__ float g_cnt_s[N_NODES];
__device__ float g_cnt_d[N_NODES];

// ---------------- helpers ----------------
__device__ __forceinline__ uint32_t smem_u32(const void* p) {
    uint32_t a;
    asm("{ .reg .u64 t; cvta.to.shared.u64 t, %1; cvt.u32.u64 %0, t; }" : "=r"(a) : "l"(p));
    return a;
}
__device__ __forceinline__ void ldsm4(uint32_t* r, uint32_t addr) {
    asm volatile("ldmatrix.sync.aligned.m8n8.x4.shared.b16 {%0,%1,%2,%3}, [%4];"
                 : "=r"(r[0]), "=r"(r[1]), "=r"(r[2]), "=r"(r[3]) : "r"(addr));
}
__device__ __forceinline__ void ldsm2(uint32_t* r, uint32_t addr) {
    asm volatile("ldmatrix.sync.aligned.m8n8.x2.shared.b16 {%0,%1}, [%2];"
                 : "=r"(r[0]), "=r"(r[1]) : "r"(addr));
}
__device__ __forceinline__ void mma16816(float* d, const uint32_t* a, const uint32_t* b) {
    asm volatile("mma.sync.aligned.m16n8k16.row.col.f32.f16.f16.f32 "
                 "{%0,%1,%2,%3}, {%4,%5,%6,%7}, {%8,%9}, {%0,%1,%2,%3};"
                 : "+f"(d[0]), "+f"(d[1]), "+f"(d[2]), "+f"(d[3])
                 : "r"(a[0]), "r"(a[1]), "r"(a[2]), "r"(a[3]), "r"(b[0]), "r"(b[1]));
}
__device__ __forceinline__ uint32_t pack_h2(float a, float b) {
    __half2 h = __floats2half2_rn(a, b);
    return *reinterpret_cast<uint32_t*>(&h);
}
// tanh-GELU via identity 0.5*x*(1+tanh(z)) == x * sigmoid(2*z)
__device__ __forceinline__ float gelu_fast(float x) {
    float z2 = 1.5957691216057308f * x * (1.0f + 0.044715f * x * x);
    return __fdividef(x, 1.0f + __expf(-z2));
}
__device__ __forceinline__ void red_add_v2(float* addr, float a, float b) {
    asm volatile("red.global.add.v2.f32 [%0], {%1,%2};"
                 :: "l"(addr), "f"(a), "f"(b) : "memory");
}

__global__ void zero_scratch_kernel() {
    int i = blockIdx.x * blockDim.x + threadIdx.x;
    int stride = gridDim.x * blockDim.x;
    const float4 z = make_float4(0.f, 0.f, 0.f, 0.f);
    for (int j = i; j < N_NODES * D / 4; j += stride) {
        ((float4*)g_acc_u)[j] = z;
        ((float4*)g_acc_v)[j] = z;
    }
    for (int j = i; j < N_NODES; j += stride) {
        g_cnt_s[j] = 0.f;
        g_cnt_d[j] = 0.f;
    }
}

template <bool EDGE>
__global__ __launch_bounds__(BLOCK, 1)
void mlp_mma_kernel(const float* __restrict__ ndata,
                    const float* __restrict__ edata,
                    const int* __restrict__ src,
                    const int* __restrict__ dst,
                    const float* __restrict__ W1,   // [192][128]
                    const float* __restrict__ b1,
                    const float* __restrict__ W2,   // [128][64]
                    const float* __restrict__ b2,
                    const float* __restrict__ gam,
                    const float* __restrict__ beta,
                    float* __restrict__ out,
                    int count) {
    extern __shared__ __align__(16) char smc[];
    const uint32_t sb = smem_u32(smc);
    const int tid = threadIdx.x;
    const int w = tid >> 5, l = tid & 31;

    // ---- stage weights transposed to [n][k], fp16 split hi/lo ----
    for (int i = tid; i < IN_F * HID; i += BLOCK) {
        int k = i >> 7, n = i & 127;
        float v = W1[i];
        __half h = __float2half_rn(v);
        __half lo = __float2half_rn(v - __half2float(h));
        uint32_t o = (uint32_t)(n * W1STR + k) * 2;
        *(__half*)(smc + W1H_OFF + o) = h;
        *(__half*)(smc + W1L_OFF + o) = lo;
    }
    for (int i = tid; i < HID * D; i += BLOCK) {
        int k = i >> 6, n = i & 63;
        float v = W2[i];
        __half h = __float2half_rn(v);
        __half lo = __float2half_rn(v - __half2float(h));
        uint32_t o = (uint32_t)(n * W2STR + k) * 2;
        *(__half*)(smc + W2H_OFF + o) = h;
        *(__half*)(smc + W2L_OFF + o) = lo;
    }
    float* b1s = (float*)(smc + B1_OFF);
    float* b2s = (float*)(smc + B2_OFF);
    float* gs = (float*)(smc + G_OFF);
    float* bts = (float*)(smc + BETA_OFF);
    for (int i = tid; i < HID; i += BLOCK) b1s[i] = b1[i];
    for (int i = tid; i < D; i += BLOCK) {
        b2s[i] = b2[i];
        gs[i] = gam[i];
        bts[i] = beta[i];
    }

    const float4* nd4 = (const float4*)ndata;
    const float4* ed4 = (const float4*)edata;

    // lane-invariant ldmatrix address pieces
    const int am = l >> 3;                     // matrix id 0..3
    const int g = l >> 2, t = l & 3;
    const int mw = w >> 3, nw = w & 7;         // GEMM1: 2 m-warps x 8 n-warps
    const uint32_t aoff1 = (uint32_t)((mw * 32 + (am & 1) * 8 + (l & 7)) * XSTR + (am >> 1) * 8) * 2;
    const uint32_t boff1 = (uint32_t)((nw * 16 + (am >> 1) * 8 + (l & 7)) * W1STR + (am & 1) * 8) * 2;
    // GEMM2 (warps 0-3 only): warp w owns rows w*16..w*16+15, all 64 cols
    const uint32_t aoff2 = (uint32_t)((w * 16 + (am & 1) * 8 + (l & 7)) * HSTR + (am >> 1) * 8) * 2;
    uint32_t b2base;
    if (l < 8)        b2base = (uint32_t)(l * W2STR) * 2;
    else if (l < 16)  b2base = (uint32_t)((l - 8) * W2STR + 8) * 2;
    else              b2base = 0;

    // gather mapping: 8 threads per row, 6 float4 slots each
    const int grow = tid >> 3;                 // 0..63
    const int gslot = tid & 7;

    const int ntiles = (count + TM - 1) / TM;

    float4 vbuf[6];

    auto load_regs = [&](int tile_) {
        int idx = tile_ * TM + grow;
        bool valid = EDGE || idx < count;
        int sI = 0, dI = 0;
        float invS = 1.f, invD = 1.f;
        if (valid) {
            if (EDGE) {
                sI = src[idx];
                dI = dst[idx];
            } else {
                invS = 1.f / fmaxf(g_cnt_s[idx], 1.f);
                invD = 1.f / fmaxf(g_cnt_d[idx], 1.f);
            }
        }
        #pragma unroll
        for (int jj = 0; jj < 6; jj++) {
            int seg = gslot + jj * 8;          // 0..47
            float4 v = make_float4(0.f, 0.f, 0.f, 0.f);
            if (valid) {
                if (EDGE) {
                    if (seg < 16)      v = nd4[(size_t)sI * 16 + seg];
                    else if (seg < 32) v = nd4[(size_t)dI * 16 + (seg - 16)];
                    else               v = ed4[(size_t)idx * 16 + (seg - 32)];
                } else {
                    if (seg < 16) {
                        float4 a = ((const float4*)g_acc_u)[(size_t)idx * 16 + seg];
                        v = make_float4(a.x * invS, a.y * invS, a.z * invS, a.w * invS);
                    } else if (seg < 32) {
                        float4 a = ((const float4*)g_acc_v)[(size_t)idx * 16 + (seg - 16)];
                        v = make_float4(a.x * invD, a.y * invD, a.z * invD, a.w * invD);
                    } else {
                        v = nd4[(size_t)idx * 16 + (seg - 32)];
                    }
                }
            }
            vbuf[jj] = v;
        }
    };
    auto store_smem = [&]() {
        #pragma unroll
        for (int jj = 0; jj < 6; jj++) {
            int seg = gslot + jj * 8;
            uint32_t o = (uint32_t)(grow * XSTR) * 2 + (uint32_t)seg * 8;
            *(uint2*)(smc + X_OFF + o) =
                make_uint2(pack_h2(vbuf[jj].x, vbuf[jj].y), pack_h2(vbuf[jj].z, vbuf[jj].w));
        }
    };

    int tile = blockIdx.x;
    if (tile < ntiles) {
        load_regs(tile);
        store_smem();
    }
    __syncthreads();

    while (tile < ntiles) {
        const int e0 = tile * TM;
        const int nxt = tile + gridDim.x;
        const bool have_next = nxt < ntiles;

        // issue next tile's LDGs early; latency hides under GEMM1
        if (have_next) load_regs(nxt);

        // ---- GEMM1: C1[64][128] = X @ (W1hi + W1lo), 2-pass fp16 ----
        float c1[2][2][4];
        #pragma unroll
        for (int mi = 0; mi < 2; mi++)
            #pragma unroll
            for (int ni = 0; ni < 2; ni++)
                #pragma unroll
                for (int q = 0; q < 4; q++) c1[mi][ni][q] = 0.f;
        #pragma unroll 2
        for (int ks = 0; ks < 12; ks++) {
            const uint32_t ko = (uint32_t)ks * 32;
            uint32_t a[2][4], bh[4], bl[4];
            ldsm4(a[0], sb + X_OFF + aoff1 + ko);
            ldsm4(a[1], sb + X_OFF + aoff1 + 16 * XSTR * 2 + ko);
            ldsm4(bh, sb + W1H_OFF + boff1 + ko);
            ldsm4(bl, sb + W1L_OFF + boff1 + ko);
            #pragma unroll
            for (int mi = 0; mi < 2; mi++)
                #pragma unroll
                for (int ni = 0; ni < 2; ni++) {
                    mma16816(c1[mi][ni], a[mi], bh + ni * 2);
                    mma16816(c1[mi][ni], a[mi], bl + ni * 2);
                }
        }

        // ---- epilogue1: +b1, fast gelu -> H fp16 smem ----
        #pragma unroll
        for (int mi = 0; mi < 2; mi++)
            #pragma unroll
            for (int ni = 0; ni < 2; ni++) {
                int colb = nw * 16 + ni * 8 + t * 2;
                #pragma unroll
                for (int h = 0; h < 2; h++) {
                    int r = mw * 32 + mi * 16 + g + h * 8;
                    float v0 = gelu_fast(c1[mi][ni][2 * h] + b1s[colb]);
                    float v1 = gelu_fast(c1[mi][ni][2 * h + 1] + b1s[colb + 1]);
                    *(uint32_t*)(smc + H_OFF + (uint32_t)(r * HSTR + colb) * 2) = pack_h2(v0, v1);
                }
            }
        __syncthreads();

        // X(tile) dead: stage X(nxt) (all warps; overlaps GEMM2 in warps 0-3)
        if (have_next) store_smem();

        // ---- GEMM2 + LN + writeout, concentrated in warps 0-3 ----
        // warp w owns rows [w*16, w*16+16), all 64 cols -> LN is intra-warp
        if (w < 4) {
            float c2[8][4];
            #pragma unroll
            for (int nb = 0; nb < 8; nb++)
                #pragma unroll
                for (int q = 0; q < 4; q++) c2[nb][q] = 0.f;
            for (int ks = 0; ks < 8; ks++) {
                const uint32_t ko = (uint32_t)ks * 32;
                uint32_t a[4];
                ldsm4(a, sb + H_OFF + aoff2 + ko);
                #pragma unroll
                for (int nb = 0; nb < 8; nb++) {
                    uint32_t bh[2], bl[2];
                    ldsm2(bh, sb + W2H_OFF + b2base + (uint32_t)nb * W2NB + ko);
                    ldsm2(bl, sb + W2L_OFF + b2base + (uint32_t)nb * W2NB + ko);
                    mma16816(c2[nb], a, bh);
                    mma16816(c2[nb], a, bl);
                }
            }

            #pragma unroll
            for (int h = 0; h < 2; h++) {
                int r = w * 16 + g + h * 8;
                int idx = e0 + r;
                // row stats: 16 vals per thread + reduce over 4-thread t-group
                float s = 0.f, q = 0.f;
                float vals[16];
                #pragma unroll
                for (int nb = 0; nb < 8; nb++) {
                    float v0 = c2[nb][2 * h] + b2s[nb * 8 + t * 2];
                    float v1 = c2[nb][2 * h + 1] + b2s[nb * 8 + t * 2 + 1];
                    vals[2 * nb] = v0;
                    vals[2 * nb + 1] = v1;
                    s += v0 + v1;
                    q += v0 * v0 + v1 * v1;
                }
                s += __shfl_xor_sync(0xffffffffu, s, 1);
                q += __shfl_xor_sync(0xffffffffu, q, 1);
                s += __shfl_xor_sync(0xffffffffu, s, 2);
                q += __shfl_xor_sync(0xffffffffu, q, 2);
                float mean = s * (1.f / 64.f);
                float var = q * (1.f / 64.f) - mean * mean;
                float rstd = rsqrtf(var + 1e-5f);

                if (EDGE || idx < count) {
                    int sN = 0, dN = 0;
                    if (EDGE) { sN = src[idx]; dN = dst[idx]; }
                    #pragma unroll
                    for (int nb = 0; nb < 8; nb++) {
                        int col = nb * 8 + t * 2;
                        float o0 = (vals[2 * nb] - mean) * rstd * gs[col] + bts[col];
                        float o1 = (vals[2 * nb + 1] - mean) * rstd * gs[col + 1] + bts[col + 1];
                        *(float2*)(out + (size_t)idx * D + col) = make_float2(o0, o1);
                        if (EDGE) {
                            red_add_v2(g_acc_u + (size_t)sN * D + col, o0, o1);
                            red_add_v2(g_acc_v + (size_t)dN * D + col, o0, o1);
                        }
                    }
                    if (EDGE && t == 0) {
                        atomicAdd(&g_cnt_s[sN], 1.f);
                        atomicAdd(&g_cnt_d[dN], 1.f);
                    }
                }
            }
        }
        __syncthreads();
        tile = nxt;
    }
}

extern "C" void kernel_launch(void* const* d_in, const int* in_sizes, int n_in,
                              void* d_out, int out_size) {
    const float* ndata = (const float*)d_in[0];
    const float* edata = (const float*)d_in[1];
    const int* src = (const int*)d_in[2];
    const int* dst = (const int*)d_in[3];
    const float* eW1 = (const float*)d_in[4];
    const float* eb1 = (const float*)d_in[5];
    const float* eW2 = (const float*)d_in[6];
    const float* eb2 = (const float*)d_in[7];
    const float* eg = (const float*)d_in[8];
    const float* ebeta = (const float*)d_in[9];
    const float* nW1 = (const float*)d_in[10];
    const float* nb1 = (const float*)d_in[11];
    const float* nW2 = (const float*)d_in[12];
    const float* nb2 = (const float*)d_in[13];
    const float* ng = (const float*)d_in[14];
    const float* nbeta = (const float*)d_in[15];

    float* out = (float*)d_out;
    float* out_nodes = out;
    float* out_edges = out + (size_t)N_NODES * D;

    void (*kE)(const float*, const float*, const int*, const int*,
               const float*, const float*, const float*, const float*,
               const float*, const float*, float*, int) = mlp_mma_kernel<true>;
    void (*kN)(const float*, const float*, const int*, const int*,
               const float*, const float*, const float*, const float*,
               const float*, const float*, float*, int) = mlp_mma_kernel<false>;
    cudaFuncSetAttribute((const void*)kE, cudaFuncAttributeMaxDynamicSharedMemorySize, SMEM_BYTES);
    cudaFuncSetAttribute((const void*)kN, cudaFuncAttributeMaxDynamicSharedMemorySize, SMEM_BYTES);

    zero_scratch_kernel<<<1024, 256>>>();
    kE<<<NBLK, BLOCK, SMEM_BYTES>>>(ndata, edata, src, dst,
                                    eW1, eb1, eW2, eb2, eg, ebeta,
                                    out_edges, N_EDGES);
    kN<<<NBLK, BLOCK, SMEM_BYTES>>>(ndata, nullptr, nullptr, nullptr,
                                    nW1, nb1, nW2, nb2, ng, nbeta,
                                    out_nodes, N_NODES);
}

// round 17
// speedup vs baseline: 2.0660x; 1.1013x over previous
#include <cuda_runtime.h>
#include <cuda_fp16.h>
#include <math.h>
#include <stdint.h>
#include <stddef.h>

#define N_NODES 50000
#define N_EDGES 800000
#define D 64
#define HID 128
#define IN_F 192
#define TM 64
#define BLOCK 512
#define NBLK 152

// padded fp16 row strides (row byte base steps by 16 mod 128 -> conflict-free ldmatrix)
#define XSTR 200     // K=192 + 8 pad
#define HSTR 136     // K=128 + 8 pad
#define W1STR 200
#define W2STR 136
#define W2NB (8 * W2STR * 2)   // byte stride between n8 blocks of W2

// ---- shared memory byte offsets ----
#define W1H_OFF 0            // [128 n][200 k] fp16 = 51200 (single precision pass)
#define W2H_OFF 51200        // [64 n][136 k] fp16 = 17408
#define W2L_OFF 68608
#define X_OFF 86016          // [64 m][200 k] fp16 = 25600 (single buffer)
#define H_OFF 111616         // [64 m][136 k] fp16 = 17408 (single buffer)
#define B1_OFF 129024        // b1[128] f32
#define B2_OFF 129536        // b2[64] f32
#define G_OFF 129792
#define BETA_OFF 130048
#define SMEM_BYTES 130304

// scratch for segment-mean aggregation
__device__ __align__(16) float g_acc_u[N_NODES * D];
__device__ __align__(16) float g_acc_v[N_NODES * D];
__device__ float g_cnt_s[N_NODES];
__device__ float g_cnt_d[N_NODES];

// ---------------- helpers ----------------
__device__ __forceinline__ uint32_t smem_u32(const void* p) {
    uint32_t a;
    asm("{ .reg .u64 t; cvta.to.shared.u64 t, %1; cvt.u32.u64 %0, t; }" : "=r"(a) : "l"(p));
    return a;
}
__device__ __forceinline__ void ldsm4(uint32_t* r, uint32_t addr) {
    asm volatile("ldmatrix.sync.aligned.m8n8.x4.shared.b16 {%0,%1,%2,%3}, [%4];"
                 : "=r"(r[0]), "=r"(r[1]), "=r"(r[2]), "=r"(r[3]) : "r"(addr));
}
__device__ __forceinline__ void ldsm2(uint32_t* r, uint32_t addr) {
    asm volatile("ldmatrix.sync.aligned.m8n8.x2.shared.b16 {%0,%1}, [%2];"
                 : "=r"(r[0]), "=r"(r[1]) : "r"(addr));
}
__device__ __forceinline__ void mma16816(float* d, const uint32_t* a, const uint32_t* b) {
    asm volatile("mma.sync.aligned.m16n8k16.row.col.f32.f16.f16.f32 "
                 "{%0,%1,%2,%3}, {%4,%5,%6,%7}, {%8,%9}, {%0,%1,%2,%3};"
                 : "+f"(d[0]), "+f"(d[1]), "+f"(d[2]), "+f"(d[3])
                 : "r"(a[0]), "r"(a[1]), "r"(a[2]), "r"(a[3]), "r"(b[0]), "r"(b[1]));
}
__device__ __forceinline__ uint32_t pack_h2(float a, float b) {
    __half2 h = __floats2half2_rn(a, b);
    return *reinterpret_cast<uint32_t*>(&h);
}
// tanh-GELU via identity 0.5*x*(1+tanh(z)) == x * sigmoid(2*z)
__device__ __forceinline__ float gelu_fast(float x) {
    float z2 = 1.5957691216057308f * x * (1.0f + 0.044715f * x * x);
    return __fdividef(x, 1.0f + __expf(-z2));
}
__device__ __forceinline__ void red_add_v2(float* addr, float a, float b) {
    asm volatile("red.global.add.v2.f32 [%0], {%1,%2};"
                 :: "l"(addr), "f"(a), "f"(b) : "memory");
}

__global__ void zero_scratch_kernel() {
    int i = blockIdx.x * blockDim.x + threadIdx.x;
    int stride = gridDim.x * blockDim.x;
    const float4 z = make_float4(0.f, 0.f, 0.f, 0.f);
    for (int j = i; j < N_NODES * D / 4; j += stride) {
        ((float4*)g_acc_u)[j] = z;
        ((float4*)g_acc_v)[j] = z;
    }
    for (int j = i; j < N_NODES; j += stride) {
        g_cnt_s[j] = 0.f;
        g_cnt_d[j] = 0.f;
    }
}

template <bool EDGE>
__global__ __launch_bounds__(BLOCK, 1)
void mlp_mma_kernel(const float* __restrict__ ndata,
                    const float* __restrict__ edata,
                    const int* __restrict__ src,
                    const int* __restrict__ dst,
                    const float* __restrict__ W1,   // [192][128]
                    const float* __restrict__ b1,
                    const float* __restrict__ W2,   // [128][64]
                    const float* __restrict__ b2,
                    const float* __restrict__ gam,
                    const float* __restrict__ beta,
                    float* __restrict__ out,
                    int count) {
    extern __shared__ __align__(16) char smc[];
    const uint32_t sb = smem_u32(smc);
    const int tid = threadIdx.x;
    const int w = tid >> 5, l = tid & 31;

    // ---- stage weights transposed to [n][k]: W1 fp16 (single), W2 hi/lo ----
    for (int i = tid; i < IN_F * HID; i += BLOCK) {
        int k = i >> 7, n = i & 127;
        uint32_t o = (uint32_t)(n * W1STR + k) * 2;
        *(__half*)(smc + W1H_OFF + o) = __float2half_rn(W1[i]);
    }
    for (int i = tid; i < HID * D; i += BLOCK) {
        int k = i >> 6, n = i & 63;
        float v = W2[i];
        __half h = __float2half_rn(v);
        __half lo = __float2half_rn(v - __half2float(h));
        uint32_t o = (uint32_t)(n * W2STR + k) * 2;
        *(__half*)(smc + W2H_OFF + o) = h;
        *(__half*)(smc + W2L_OFF + o) = lo;
    }
    float* b1s = (float*)(smc + B1_OFF);
    float* b2s = (float*)(smc + B2_OFF);
    float* gs = (float*)(smc + G_OFF);
    float* bts = (float*)(smc + BETA_OFF);
    for (int i = tid; i < HID; i += BLOCK) b1s[i] = b1[i];
    for (int i = tid; i < D; i += BLOCK) {
        b2s[i] = b2[i];
        gs[i] = gam[i];
        bts[i] = beta[i];
    }

    const float4* nd4 = (const float4*)ndata;
    const float4* ed4 = (const float4*)edata;

    // lane-invariant ldmatrix address pieces
    const int am = l >> 3;                     // matrix id 0..3
    const int g = l >> 2, t = l & 3;
    const int mw = w >> 3, nw = w & 7;         // GEMM1: 2 m-warps x 8 n-warps
    const uint32_t aoff1 = (uint32_t)((mw * 32 + (am & 1) * 8 + (l & 7)) * XSTR + (am >> 1) * 8) * 2;
    const uint32_t boff1 = (uint32_t)((nw * 16 + (am >> 1) * 8 + (l & 7)) * W1STR + (am & 1) * 8) * 2;
    // GEMM2 (warps 0-3 only): warp w owns rows w*16..w*16+15, all 64 cols
    const uint32_t aoff2 = (uint32_t)((w * 16 + (am & 1) * 8 + (l & 7)) * HSTR + (am >> 1) * 8) * 2;
    uint32_t b2base;
    if (l < 8)        b2base = (uint32_t)(l * W2STR) * 2;
    else if (l < 16)  b2base = (uint32_t)((l - 8) * W2STR + 8) * 2;
    else              b2base = 0;

    // gather mapping: 8 threads per row, 6 float4 slots each
    const int grow = tid >> 3;                 // 0..63
    const int gslot = tid & 7;

    const int ntiles = (count + TM - 1) / TM;

    float4 vbuf[6];

    auto load_regs = [&](int tile_) {
        int idx = tile_ * TM + grow;
        bool valid = EDGE || idx < count;
        int sI = 0, dI = 0;
        float invS = 1.f, invD = 1.f;
        if (valid) {
            if (EDGE) {
                sI = src[idx];
                dI = dst[idx];
            } else {
                invS = 1.f / fmaxf(g_cnt_s[idx], 1.f);
                invD = 1.f / fmaxf(g_cnt_d[idx], 1.f);
            }
        }
        #pragma unroll
        for (int jj = 0; jj < 6; jj++) {
            int seg = gslot + jj * 8;          // 0..47
            float4 v = make_float4(0.f, 0.f, 0.f, 0.f);
            if (valid) {
                if (EDGE) {
                    if (seg < 16)      v = nd4[(size_t)sI * 16 + seg];
                    else if (seg < 32) v = nd4[(size_t)dI * 16 + (seg - 16)];
                    else               v = ed4[(size_t)idx * 16 + (seg - 32)];
                } else {
                    if (seg < 16) {
                        float4 a = ((const float4*)g_acc_u)[(size_t)idx * 16 + seg];
                        v = make_float4(a.x * invS, a.y * invS, a.z * invS, a.w * invS);
                    } else if (seg < 32) {
                        float4 a = ((const float4*)g_acc_v)[(size_t)idx * 16 + (seg - 16)];
                        v = make_float4(a.x * invD, a.y * invD, a.z * invD, a.w * invD);
                    } else {
                        v = nd4[(size_t)idx * 16 + (seg - 32)];
                    }
                }
            }
            vbuf[jj] = v;
        }
    };
    auto store_smem = [&]() {
        #pragma unroll
        for (int jj = 0; jj < 6; jj++) {
            int seg = gslot + jj * 8;
            uint32_t o = (uint32_t)(grow * XSTR) * 2 + (uint32_t)seg * 8;
            *(uint2*)(smc + X_OFF + o) =
                make_uint2(pack_h2(vbuf[jj].x, vbuf[jj].y), pack_h2(vbuf[jj].z, vbuf[jj].w));
        }
    };

    int tile = blockIdx.x;
    if (tile < ntiles) {
        load_regs(tile);
        store_smem();
    }
    __syncthreads();

    while (tile < ntiles) {
        const int e0 = tile * TM;
        const int nxt = tile + gridDim.x;
        const bool have_next = nxt < ntiles;

        // issue next tile's LDGs early; latency hides under GEMM1
        if (have_next) load_regs(nxt);

        // ---- GEMM1: C1[64][128] = X @ W1 (single-pass fp16) ----
        float c1[2][2][4];
        #pragma unroll
        for (int mi = 0; mi < 2; mi++)
            #pragma unroll
            for (int ni = 0; ni < 2; ni++)
                #pragma unroll
                for (int q = 0; q < 4; q++) c1[mi][ni][q] = 0.f;
        #pragma unroll 2
        for (int ks = 0; ks < 12; ks++) {
            const uint32_t ko = (uint32_t)ks * 32;
            uint32_t a[2][4], bh[4];
            ldsm4(a[0], sb + X_OFF + aoff1 + ko);
            ldsm4(a[1], sb + X_OFF + aoff1 + 16 * XSTR * 2 + ko);
            ldsm4(bh, sb + W1H_OFF + boff1 + ko);
            #pragma unroll
            for (int mi = 0; mi < 2; mi++)
                #pragma unroll
                for (int ni = 0; ni < 2; ni++)
                    mma16816(c1[mi][ni], a[mi], bh + ni * 2);
        }

        // ---- epilogue1: +b1, fast gelu -> H fp16 smem ----
        #pragma unroll
        for (int mi = 0; mi < 2; mi++)
            #pragma unroll
            for (int ni = 0; ni < 2; ni++) {
                int colb = nw * 16 + ni * 8 + t * 2;
                #pragma unroll
                for (int h = 0; h < 2; h++) {
                    int r = mw * 32 + mi * 16 + g + h * 8;
                    float v0 = gelu_fast(c1[mi][ni][2 * h] + b1s[colb]);
                    float v1 = gelu_fast(c1[mi][ni][2 * h + 1] + b1s[colb + 1]);
                    *(uint32_t*)(smc + H_OFF + (uint32_t)(r * HSTR + colb) * 2) = pack_h2(v0, v1);
                }
            }
        __syncthreads();

        // X(tile) dead: stage X(nxt) (all warps; overlaps GEMM2 in warps 0-3)
        if (have_next) store_smem();

        // ---- GEMM2 + LN + writeout, concentrated in warps 0-3 ----
        // warp w owns rows [w*16, w*16+16), all 64 cols -> LN is intra-warp
        if (w < 4) {
            float c2[8][4];
            #pragma unroll
            for (int nb = 0; nb < 8; nb++)
                #pragma unroll
                for (int q = 0; q < 4; q++) c2[nb][q] = 0.f;
            for (int ks = 0; ks < 8; ks++) {
                const uint32_t ko = (uint32_t)ks * 32;
                uint32_t a[4];
                ldsm4(a, sb + H_OFF + aoff2 + ko);
                #pragma unroll
                for (int nb = 0; nb < 8; nb++) {
                    uint32_t bh[2], bl[2];
                    ldsm2(bh, sb + W2H_OFF + b2base + (uint32_t)nb * W2NB + ko);
                    ldsm2(bl, sb + W2L_OFF + b2base + (uint32_t)nb * W2NB + ko);
                    mma16816(c2[nb], a, bh);
                    mma16816(c2[nb], a, bl);
                }
            }

            #pragma unroll
            for (int h = 0; h < 2; h++) {
                int r = w * 16 + g + h * 8;
                int idx = e0 + r;
                // row stats: 16 vals per thread + reduce over 4-thread t-group
                float s = 0.f, q = 0.f;
                float vals[16];
                #pragma unroll
                for (int nb = 0; nb < 8; nb++) {
                    float v0 = c2[nb][2 * h] + b2s[nb * 8 + t * 2];
                    float v1 = c2[nb][2 * h + 1] + b2s[nb * 8 + t * 2 + 1];
                    vals[2 * nb] = v0;
                    vals[2 * nb + 1] = v1;
                    s += v0 + v1;
                    q += v0 * v0 + v1 * v1;
                }
                s += __shfl_xor_sync(0xffffffffu, s, 1);
                q += __shfl_xor_sync(0xffffffffu, q, 1);
                s += __shfl_xor_sync(0xffffffffu, s, 2);
                q += __shfl_xor_sync(0xffffffffu, q, 2);
                float mean = s * (1.f / 64.f);
                float var = q * (1.f / 64.f) - mean * mean;
                float rstd = rsqrtf(var + 1e-5f);

                if (EDGE || idx < count) {
                    int sN = 0, dN = 0;
                    if (EDGE) { sN = src[idx]; dN = dst[idx]; }
                    #pragma unroll
                    for (int nb = 0; nb < 8; nb++) {
                        int col = nb * 8 + t * 2;
                        float o0 = (vals[2 * nb] - mean) * rstd * gs[col] + bts[col];
                        float o1 = (vals[2 * nb + 1] - mean) * rstd * gs[col + 1] + bts[col + 1];
                        *(float2*)(out + (size_t)idx * D + col) = make_float2(o0, o1);
                        if (EDGE) {
                            red_add_v2(g_acc_u + (size_t)sN * D + col, o0, o1);
                            red_add_v2(g_acc_v + (size_t)dN * D + col, o0, o1);
                        }
                    }
                    if (EDGE && t == 0) {
                        atomicAdd(&g_cnt_s[sN], 1.f);
                        atomicAdd(&g_cnt_d[dN], 1.f);
                    }
                }
            }
        }
        __syncthreads();
        tile = nxt;
    }
}

extern "C" void kernel_launch(void* const* d_in, const int* in_sizes, int n_in,
                              void* d_out, int out_size) {
    const float* ndata = (const float*)d_in[0];
    const float* edata = (const float*)d_in[1];
    const int* src = (const int*)d_in[2];
    const int* dst = (const int*)d_in[3];
    const float* eW1 = (const float*)d_in[4];
    const float* eb1 = (const float*)d_in[5];
    const float* eW2 = (const float*)d_in[6];
    const float* eb2 = (const float*)d_in[7];
    const float* eg = (const float*)d_in[8];
    const float* ebeta = (const float*)d_in[9];
    const float* nW1 = (const float*)d_in[10];
    const float* nb1 = (const float*)d_in[11];
    const float* nW2 = (const float*)d_in[12];
    const float* nb2 = (const float*)d_in[13];
    const float* ng = (const float*)d_in[14];
    const float* nbeta = (const float*)d_in[15];

    float* out = (float*)d_out;
    float* out_nodes = out;
    float* out_edges = out + (size_t)N_NODES * D;

    void (*kE)(const float*, const float*, const int*, const int*,
               const float*, const float*, const float*, const float*,
               const float*, const float*, float*, int) = mlp_mma_kernel<true>;
    void (*kN)(const float*, const float*, const int*, const int*,
               const float*, const float*, const float*, const float*,
               const float*, const float*, float*, int) = mlp_mma_kernel<false>;
    cudaFuncSetAttribute((const void*)kE, cudaFuncAttributeMaxDynamicSharedMemorySize, SMEM_BYTES);
    cudaFuncSetAttribute((const void*)kN, cudaFuncAttributeMaxDynamicSharedMemorySize, SMEM_BYTES);

    zero_scratch_kernel<<<1024, 256>>>();
    kE<<<NBLK, BLOCK, SMEM_BYTES>>>(ndata, edata, src, dst,
                                    eW1, eb1, eW2, eb2, eg, ebeta,
                                    out_edges, N_EDGES);
    kN<<<NBLK, BLOCK, SMEM_BYTES>>>(ndata, nullptr, nullptr, nullptr,
                                    nW1, nb1, nW2, nb2, ng, nbeta,
                                    out_nodes, N_NODES);
}